// round 1
// baseline (speedup 1.0000x reference)
#include <cuda_runtime.h>
#include <math.h>

#define D 128
#define NH 4
#define MAXN 100352
#define MAXE 1700000

// ---------------- scratch (static device globals; no allocations) -------------
__device__ float g_xl[MAXN * D];
__device__ float g_xr[MAXN * D];
__device__ float g_h[MAXN * D];
__device__ int   g_src[MAXE];
__device__ int   g_counts[MAXN];
__device__ int   g_starts[MAXN];
__device__ int   g_cursor[MAXN];
__device__ int   g_is64;

// ---------------- edge-index dtype detection ---------------------------------
// If edge_index is int64 little-endian, every odd 32-bit word (hi half) is 0.
// If int32, odd words are random node ids in [0,100000): P(all 32 zero) ~ 0.
__global__ void k_detect(const unsigned int* __restrict__ e) {
    unsigned int w = e[2 * threadIdx.x + 1];
    unsigned int b = __ballot_sync(0xffffffffu, w == 0u);
    if (threadIdx.x == 0) g_is64 = (b == 0xffffffffu) ? 1 : 0;
}

__global__ void k_zero(int n) {
    int i = blockIdx.x * blockDim.x + threadIdx.x;
    if (i < n) g_counts[i] = 0;
}

__device__ __forceinline__ int edge_at(const void* e, int is64, long long idx) {
    if (is64) return (int)((const long long*)e)[idx];
    return ((const int*)e)[idx];
}

__global__ void k_hist(const void* __restrict__ e, long long E) {
    long long i = (long long)blockIdx.x * blockDim.x + threadIdx.x;
    if (i >= E) return;
    int is64 = g_is64;
    int d = edge_at(e, is64, E + i);
    atomicAdd(&g_counts[d], 1);
}

// Single-block exclusive scan of counts -> starts (and cursor copy).
__global__ __launch_bounds__(1024) void k_scan(int n) {
    __shared__ int ssum[1024];
    int t = threadIdx.x;
    int ch = (n + 1023) >> 10;
    int b = t * ch;
    int e = b + ch; if (e > n) e = n;
    int s = 0;
    for (int i = b; i < e; i++) s += g_counts[i];
    ssum[t] = s;
    __syncthreads();
    for (int off = 1; off < 1024; off <<= 1) {
        int v = (t >= off) ? ssum[t - off] : 0;
        __syncthreads();
        ssum[t] += v;
        __syncthreads();
    }
    int run = (t == 0) ? 0 : ssum[t - 1];
    for (int i = b; i < e; i++) {
        g_starts[i] = run;
        g_cursor[i] = run;
        run += g_counts[i];
    }
}

__global__ void k_scatter(const void* __restrict__ e, long long E) {
    long long i = (long long)blockIdx.x * blockDim.x + threadIdx.x;
    if (i >= E) return;
    int is64 = g_is64;
    int s = edge_at(e, is64, i);
    int d = edge_at(e, is64, E + i);
    int pos = atomicAdd(&g_cursor[d], 1);
    g_src[pos] = s;
}

// ---------------- GEMM: out[M,128] = A[M,128] @ W[128,128] -------------------
// 64-row tile, full K=128 and N=128 staged in smem. Per-thread 4m x 8n
// register tile accumulated as packed fp32x2 via fma.rn.f32x2 (2x FFMA rate).
__device__ __forceinline__ void fma2(unsigned long long& c, unsigned long long a,
                                     unsigned long long b) {
    asm("fma.rn.f32x2 %0, %1, %2, %0;" : "+l"(c) : "l"(a), "l"(b));
}
__device__ __forceinline__ unsigned long long pack2(float a) {
    unsigned long long r;
    asm("mov.b64 %0, {%1, %1};" : "=l"(r) : "f"(a));
    return r;
}

__global__ __launch_bounds__(256) void k_gemm(const float* __restrict__ A_ext,
                                              int a_internal,
                                              const float* __restrict__ WL,
                                              const float* __restrict__ WR,
                                              int M) {
    __shared__ float sA[64 * D];
    __shared__ float sB[D * D];
    const float* A = a_internal ? g_h : A_ext;
    const float* W = blockIdx.y ? WR : WL;
    float* Out = blockIdx.y ? g_xr : g_xl;
    int row0 = blockIdx.x * 64;
    int tid = threadIdx.x;

#pragma unroll
    for (int j = 0; j < 16; j++) {
        int idx = tid + j * 256;  // 4096 float4 = 128x128
        ((float4*)sB)[idx] = ((const float4*)W)[idx];
    }
#pragma unroll
    for (int j = 0; j < 8; j++) {
        int idx = tid + j * 256;  // 2048 float4 = 64x128
        int r = idx >> 5;
        int c = idx & 31;
        float4 v = make_float4(0.f, 0.f, 0.f, 0.f);
        if (row0 + r < M) v = ((const float4*)(A + (long long)(row0 + r) * D))[c];
        ((float4*)sA)[idx] = v;
    }
    __syncthreads();

    int nt = tid & 15, mt = tid >> 4;
    int m0 = mt * 4;
    int n0 = nt * 2;  // column pairs n0, n0+32, n0+64, n0+96 (conflict-free LDS.64)
    unsigned long long acc[4][4];
#pragma unroll
    for (int i = 0; i < 4; i++)
#pragma unroll
        for (int j = 0; j < 4; j++) acc[i][j] = 0ull;

#pragma unroll 8
    for (int k = 0; k < 128; k++) {
        unsigned long long b0 = *(const unsigned long long*)&sB[k * D + n0];
        unsigned long long b1 = *(const unsigned long long*)&sB[k * D + n0 + 32];
        unsigned long long b2 = *(const unsigned long long*)&sB[k * D + n0 + 64];
        unsigned long long b3 = *(const unsigned long long*)&sB[k * D + n0 + 96];
#pragma unroll
        for (int i = 0; i < 4; i++) {
            unsigned long long ap = pack2(sA[(m0 + i) * D + k]);
            fma2(acc[i][0], ap, b0);
            fma2(acc[i][1], ap, b1);
            fma2(acc[i][2], ap, b2);
            fma2(acc[i][3], ap, b3);
        }
    }

#pragma unroll
    for (int i = 0; i < 4; i++) {
        int row = row0 + m0 + i;
        if (row < M) {
#pragma unroll
            for (int j = 0; j < 4; j++)
                *(unsigned long long*)&Out[(long long)row * D + n0 + 32 * j] = acc[i][j];
        }
    }
}

// ---------------- fused edge attention + aggregate + LN + ELU + residual -----
__device__ __forceinline__ float edge_alpha(float4 xl4, float4 xr4, float4 at4) {
    float t0 = xl4.x + xr4.x; t0 = fmaxf(t0, 0.2f * t0);
    float t1 = xl4.y + xr4.y; t1 = fmaxf(t1, 0.2f * t1);
    float t2 = xl4.z + xr4.z; t2 = fmaxf(t2, 0.2f * t2);
    float t3 = xl4.w + xr4.w; t3 = fmaxf(t3, 0.2f * t3);
    float p = t0 * at4.x + t1 * at4.y + t2 * at4.z + t3 * at4.w;
    // reduce within 8-lane head group (lanes l..l+7 share head = lane/8)
    p += __shfl_xor_sync(0xffffffffu, p, 1);
    p += __shfl_xor_sync(0xffffffffu, p, 2);
    p += __shfl_xor_sync(0xffffffffu, p, 4);
    return p;
}

__global__ __launch_bounds__(256) void k_edge(const float* __restrict__ hin_ext,
                                              int hin_internal,
                                              float* __restrict__ hout_ext,
                                              int hout_internal,
                                              const float* __restrict__ att,
                                              const float* __restrict__ bias,
                                              const float* __restrict__ gamma,
                                              const float* __restrict__ beta,
                                              int n) {
    int node = (blockIdx.x * blockDim.x + threadIdx.x) >> 5;
    int lane = threadIdx.x & 31;
    if (node >= n) return;
    const float* hin = hin_internal ? g_h : hin_ext;
    float* hout = hout_internal ? g_h : hout_ext;
    const int c0 = lane * 4;  // channels c0..c0+3; head = lane/8

    float4 xr4 = *(const float4*)&g_xr[(long long)node * D + c0];
    float4 at4 = *(const float4*)&att[c0];

    // self-loop initializes online softmax state
    float4 xv = *(const float4*)&g_xl[(long long)node * D + c0];
    float m = edge_alpha(xv, xr4, at4);
    float s = 1.0f;
    float a0 = xv.x, a1 = xv.y, a2 = xv.z, a3 = xv.w;

    int beg = g_starts[node];
    int cnt = g_counts[node];
    float4 nxt = make_float4(0.f, 0.f, 0.f, 0.f);
    if (cnt > 0) {
        int s0 = g_src[beg];
        nxt = *(const float4*)&g_xl[(long long)s0 * D + c0];
    }
    for (int k = 0; k < cnt; k++) {
        float4 cur = nxt;
        if (k + 1 < cnt) {
            int sn = g_src[beg + k + 1];
            nxt = *(const float4*)&g_xl[(long long)sn * D + c0];
        }
        float alpha = edge_alpha(cur, xr4, at4);
        float nm = fmaxf(m, alpha);
        float sc = __expf(m - nm);
        float p = __expf(alpha - nm);
        s = s * sc + p;
        a0 = a0 * sc + p * cur.x;
        a1 = a1 * sc + p * cur.y;
        a2 = a2 * sc + p * cur.z;
        a3 = a3 * sc + p * cur.w;
        m = nm;
    }

    float4 bi4 = *(const float4*)&bias[c0];
    float inv = 1.0f / s;
    float gg0 = a0 * inv + bi4.x;
    float gg1 = a1 * inv + bi4.y;
    float gg2 = a2 * inv + bi4.z;
    float gg3 = a3 * inv + bi4.w;

    // LayerNorm across 128 channels (full-warp reduce)
    float lsum = gg0 + gg1 + gg2 + gg3;
#pragma unroll
    for (int off = 16; off >= 1; off >>= 1) lsum += __shfl_xor_sync(0xffffffffu, lsum, off);
    float mean = lsum * (1.0f / 128.0f);
    float d0 = gg0 - mean, d1 = gg1 - mean, d2 = gg2 - mean, d3 = gg3 - mean;
    float lsq = d0 * d0 + d1 * d1 + d2 * d2 + d3 * d3;
#pragma unroll
    for (int off = 16; off >= 1; off >>= 1) lsq += __shfl_xor_sync(0xffffffffu, lsq, off);
    float var = lsq * (1.0f / 128.0f);
    float rstd = rsqrtf(var + 1e-5f);

    float4 ga4 = *(const float4*)&gamma[c0];
    float4 be4 = *(const float4*)&beta[c0];
    float y0 = d0 * rstd * ga4.x + be4.x;
    float y1 = d1 * rstd * ga4.y + be4.y;
    float y2 = d2 * rstd * ga4.z + be4.z;
    float y3 = d3 * rstd * ga4.w + be4.w;
    // ELU
    y0 = (y0 > 0.f) ? y0 : expm1f(y0);
    y1 = (y1 > 0.f) ? y1 : expm1f(y1);
    y2 = (y2 > 0.f) ? y2 : expm1f(y2);
    y3 = (y3 > 0.f) ? y3 : expm1f(y3);

    float4 hv = *(const float4*)&hin[(long long)node * D + c0];
    float4 o;
    o.x = hv.x + y0;
    o.y = hv.y + y1;
    o.z = hv.z + y2;
    o.w = hv.w + y3;
    *(float4*)&hout[(long long)node * D + c0] = o;
}

// ---------------- launch ------------------------------------------------------
extern "C" void kernel_launch(void* const* d_in, const int* in_sizes, int n_in,
                              void* d_out, int out_size) {
    const float* x = (const float*)d_in[0];
    const void* ei = (const void*)d_in[1];
    const float* Wl = (const float*)d_in[2];
    const float* Wr = (const float*)d_in[3];
    const float* att = (const float*)d_in[4];
    const float* bias = (const float*)d_in[5];
    const float* gamma = (const float*)d_in[6];
    const float* beta = (const float*)d_in[7];
    float* out = (float*)d_out;

    int N = in_sizes[0] / D;
    long long E = (long long)in_sizes[1] / 2;

    // sort edges by destination (counting sort), detect index dtype
    k_detect<<<1, 32>>>((const unsigned int*)ei);
    k_zero<<<(N + 255) / 256, 256>>>(N);
    int eg = (int)((E + 255) / 256);
    k_hist<<<eg, 256>>>(ei, E);
    k_scan<<<1, 1024>>>(N);
    k_scatter<<<eg, 256>>>(ei, E);

    dim3 gg((N + 63) / 64, 2);
    int ewarps = (N + 7) / 8;  // 8 warps per 256-thread block

    // layer 0: h = x (external)
    k_gemm<<<gg, 256>>>(x, 0, Wl, Wr, N);
    k_edge<<<ewarps, 256>>>(x, 0, out, 1 /*-> g_h*/, att, bias, gamma, beta, N);
    // layer 1: h = g_h (internal), output -> d_out
    k_gemm<<<gg, 256>>>(x, 1, Wl + D * D, Wr + D * D, N);
    k_edge<<<ewarps, 256>>>(x, 1, out, 0, att + NH * 32, bias + D, gamma + D,
                            beta + D, N);
}

// round 2
// speedup vs baseline: 1.9162x; 1.9162x over previous
#include <cuda_runtime.h>
#include <math.h>

#define D 128
#define NH 4
#define MAXN 100352
#define MAXE 1700000
#define SAS 129  // padded sA row stride (bank-conflict-free)

// ---------------- scratch (static device globals; no allocations) -------------
__device__ float g_xl[MAXN * D];
__device__ float g_xr[MAXN * D];
__device__ float g_h[MAXN * D];
__device__ int   g_src[MAXE];
__device__ int   g_counts[MAXN];
__device__ int   g_starts[MAXN];
__device__ int   g_cursor[MAXN];
__device__ int   g_bsum[128];
__device__ int   g_boff[128];
__device__ int   g_is64;

// ---------------- edge-index dtype detection ---------------------------------
__global__ void k_detect(const unsigned int* __restrict__ e) {
    unsigned int w = e[2 * threadIdx.x + 1];
    unsigned int b = __ballot_sync(0xffffffffu, w == 0u);
    if (threadIdx.x == 0) g_is64 = (b == 0xffffffffu) ? 1 : 0;
}

__global__ void k_zero(int n) {
    int i = blockIdx.x * blockDim.x + threadIdx.x;
    if (i < n) g_counts[i] = 0;
}

__device__ __forceinline__ int edge_at(const void* e, int is64, long long idx) {
    if (is64) return (int)((const long long*)e)[idx];
    return ((const int*)e)[idx];
}

__global__ void k_hist(const void* __restrict__ e, long long E) {
    long long i = (long long)blockIdx.x * blockDim.x + threadIdx.x;
    if (i >= E) return;
    int is64 = g_is64;
    int d = edge_at(e, is64, E + i);
    atomicAdd(&g_counts[d], 1);
}

// ---- hierarchical scan: blksum -> tiny scan -> starts -----------------------
__global__ __launch_bounds__(256) void k_blksum(int n) {
    __shared__ int sh[256];
    int b = blockIdx.x, t = threadIdx.x;
    int base = b * 1024;
    int s = 0;
#pragma unroll
    for (int j = 0; j < 4; j++) {
        int i = base + t + j * 256;
        if (i < n) s += g_counts[i];
    }
    sh[t] = s;
    __syncthreads();
    for (int off = 128; off >= 1; off >>= 1) {
        if (t < off) sh[t] += sh[t + off];
        __syncthreads();
    }
    if (t == 0) g_bsum[b] = sh[0];
}

__global__ __launch_bounds__(128) void k_scan2(int nb) {
    __shared__ int sh[128];
    int t = threadIdx.x;
    sh[t] = (t < nb) ? g_bsum[t] : 0;
    __syncthreads();
    if (t == 0) {
        int run = 0;
        for (int i = 0; i < nb; i++) {
            int c = sh[i];
            g_boff[i] = run;
            run += c;
        }
    }
}

__global__ __launch_bounds__(256) void k_starts(int n) {
    __shared__ int ssum[256];
    int b = blockIdx.x, t = threadIdx.x;
    int base = b * 1024 + t * 4;
    int c0 = 0, c1 = 0, c2 = 0, c3 = 0;
    if (base + 0 < n) c0 = g_counts[base + 0];
    if (base + 1 < n) c1 = g_counts[base + 1];
    if (base + 2 < n) c2 = g_counts[base + 2];
    if (base + 3 < n) c3 = g_counts[base + 3];
    ssum[t] = c0 + c1 + c2 + c3;
    __syncthreads();
    // Hillis-Steele inclusive scan over 256 partials
    for (int off = 1; off < 256; off <<= 1) {
        int v = (t >= off) ? ssum[t - off] : 0;
        __syncthreads();
        ssum[t] += v;
        __syncthreads();
    }
    int run = g_boff[b] + ((t == 0) ? 0 : ssum[t - 1]);
    if (base + 0 < n) { g_starts[base + 0] = run; g_cursor[base + 0] = run; run += c0; }
    if (base + 1 < n) { g_starts[base + 1] = run; g_cursor[base + 1] = run; run += c1; }
    if (base + 2 < n) { g_starts[base + 2] = run; g_cursor[base + 2] = run; run += c2; }
    if (base + 3 < n) { g_starts[base + 3] = run; g_cursor[base + 3] = run; run += c3; }
}

__global__ void k_scatter(const void* __restrict__ e, long long E) {
    long long i = (long long)blockIdx.x * blockDim.x + threadIdx.x;
    if (i >= E) return;
    int is64 = g_is64;
    int s = edge_at(e, is64, i);
    int d = edge_at(e, is64, E + i);
    int pos = atomicAdd(&g_cursor[d], 1);
    g_src[pos] = s;
}

// ---------------- GEMM: out[M,128] = A[M,128] @ W[128,128] -------------------
__device__ __forceinline__ void fma2(unsigned long long& c, unsigned long long a,
                                     unsigned long long b) {
    asm("fma.rn.f32x2 %0, %1, %2, %0;" : "+l"(c) : "l"(a), "l"(b));
}
__device__ __forceinline__ unsigned long long pack2(float a) {
    unsigned long long r;
    asm("mov.b64 %0, {%1, %1};" : "=l"(r) : "f"(a));
    return r;
}

__global__ __launch_bounds__(256) void k_gemm(const float* __restrict__ A_ext,
                                              int a_internal,
                                              const float* __restrict__ WL,
                                              const float* __restrict__ WR,
                                              int M) {
    __shared__ float sA[64 * SAS];
    __shared__ float sB[D * D];
    const float* A = a_internal ? g_h : A_ext;
    const float* W = blockIdx.y ? WR : WL;
    float* Out = blockIdx.y ? g_xr : g_xl;
    int row0 = blockIdx.x * 64;
    int tid = threadIdx.x;

#pragma unroll
    for (int j = 0; j < 16; j++) {
        int idx = tid + j * 256;  // 4096 float4 = 128x128
        ((float4*)sB)[idx] = ((const float4*)W)[idx];
    }
#pragma unroll
    for (int j = 0; j < 8; j++) {
        int idx = tid + j * 256;  // 2048 float4 = 64 rows x 32 float4
        int r = idx >> 5;
        int c = idx & 31;
        float4 v = make_float4(0.f, 0.f, 0.f, 0.f);
        if (row0 + r < M) v = ((const float4*)(A + (long long)(row0 + r) * D))[c];
        sA[r * SAS + c * 4 + 0] = v.x;
        sA[r * SAS + c * 4 + 1] = v.y;
        sA[r * SAS + c * 4 + 2] = v.z;
        sA[r * SAS + c * 4 + 3] = v.w;
    }
    __syncthreads();

    int nt = tid & 15, mt = tid >> 4;
    int m0 = mt * 4;
    int n0 = nt * 2;
    unsigned long long acc[4][4];
#pragma unroll
    for (int i = 0; i < 4; i++)
#pragma unroll
        for (int j = 0; j < 4; j++) acc[i][j] = 0ull;

#pragma unroll 8
    for (int k = 0; k < 128; k++) {
        unsigned long long b0 = *(const unsigned long long*)&sB[k * D + n0];
        unsigned long long b1 = *(const unsigned long long*)&sB[k * D + n0 + 32];
        unsigned long long b2 = *(const unsigned long long*)&sB[k * D + n0 + 64];
        unsigned long long b3 = *(const unsigned long long*)&sB[k * D + n0 + 96];
#pragma unroll
        for (int i = 0; i < 4; i++) {
            unsigned long long ap = pack2(sA[(m0 + i) * SAS + k]);
            fma2(acc[i][0], ap, b0);
            fma2(acc[i][1], ap, b1);
            fma2(acc[i][2], ap, b2);
            fma2(acc[i][3], ap, b3);
        }
    }

#pragma unroll
    for (int i = 0; i < 4; i++) {
        int row = row0 + m0 + i;
        if (row < M) {
#pragma unroll
            for (int j = 0; j < 4; j++)
                *(unsigned long long*)&Out[(long long)row * D + n0 + 32 * j] = acc[i][j];
        }
    }
}

// ---------------- fused edge attention + aggregate + LN + ELU + residual -----
__device__ __forceinline__ float edge_alpha(float4 xl4, float4 xr4, float4 at4) {
    float t0 = xl4.x + xr4.x; t0 = fmaxf(t0, 0.2f * t0);
    float t1 = xl4.y + xr4.y; t1 = fmaxf(t1, 0.2f * t1);
    float t2 = xl4.z + xr4.z; t2 = fmaxf(t2, 0.2f * t2);
    float t3 = xl4.w + xr4.w; t3 = fmaxf(t3, 0.2f * t3);
    float p = t0 * at4.x + t1 * at4.y + t2 * at4.z + t3 * at4.w;
    p += __shfl_xor_sync(0xffffffffu, p, 1);
    p += __shfl_xor_sync(0xffffffffu, p, 2);
    p += __shfl_xor_sync(0xffffffffu, p, 4);
    return p;
}

struct SoftState {
    float m, s, a0, a1, a2, a3;
};

__device__ __forceinline__ void upd(SoftState& st, float4 cur, float4 xr4,
                                    float4 at4) {
    float alpha = edge_alpha(cur, xr4, at4);
    float nm = fmaxf(st.m, alpha);
    float sc = __expf(st.m - nm);
    float p = __expf(alpha - nm);
    st.s = st.s * sc + p;
    st.a0 = st.a0 * sc + p * cur.x;
    st.a1 = st.a1 * sc + p * cur.y;
    st.a2 = st.a2 * sc + p * cur.z;
    st.a3 = st.a3 * sc + p * cur.w;
    st.m = nm;
}

__global__ __launch_bounds__(256) void k_edge(const float* __restrict__ hin_ext,
                                              int hin_internal,
                                              float* __restrict__ hout_ext,
                                              int hout_internal,
                                              const float* __restrict__ att,
                                              const float* __restrict__ bias,
                                              const float* __restrict__ gamma,
                                              const float* __restrict__ beta,
                                              int n) {
    int node = (blockIdx.x * blockDim.x + threadIdx.x) >> 5;
    int lane = threadIdx.x & 31;
    if (node >= n) return;
    const float* hin = hin_internal ? g_h : hin_ext;
    float* hout = hout_internal ? g_h : hout_ext;
    const int c0 = lane * 4;

    float4 xr4 = *(const float4*)&g_xr[(long long)node * D + c0];
    float4 at4 = *(const float4*)&att[c0];

    // state 0: self-loop; state 1: empty
    float4 xv = *(const float4*)&g_xl[(long long)node * D + c0];
    SoftState s0, s1;
    s0.m = edge_alpha(xv, xr4, at4);
    s0.s = 1.0f;
    s0.a0 = xv.x; s0.a1 = xv.y; s0.a2 = xv.z; s0.a3 = xv.w;
    s1.m = -1e30f; s1.s = 0.f;
    s1.a0 = 0.f; s1.a1 = 0.f; s1.a2 = 0.f; s1.a3 = 0.f;

    int beg = g_starts[node];
    int cnt = g_counts[node];

    float4 pf0 = make_float4(0.f, 0.f, 0.f, 0.f);
    float4 pf1 = make_float4(0.f, 0.f, 0.f, 0.f);
    if (cnt > 0) pf0 = *(const float4*)&g_xl[(long long)g_src[beg] * D + c0];
    if (cnt > 1) pf1 = *(const float4*)&g_xl[(long long)g_src[beg + 1] * D + c0];

    int k = 0;
    for (; k + 1 < cnt; k += 2) {
        float4 c0v = pf0, c1v = pf1;
        if (k + 2 < cnt) pf0 = *(const float4*)&g_xl[(long long)g_src[beg + k + 2] * D + c0];
        if (k + 3 < cnt) pf1 = *(const float4*)&g_xl[(long long)g_src[beg + k + 3] * D + c0];
        upd(s0, c0v, xr4, at4);
        upd(s1, c1v, xr4, at4);
    }
    if (k < cnt) upd(s0, pf0, xr4, at4);  // odd tail (lives in pf0)

    // merge the two states
    float M = fmaxf(s0.m, s1.m);
    float e0 = __expf(s0.m - M), e1 = __expf(s1.m - M);
    float s = s0.s * e0 + s1.s * e1;
    float a0 = s0.a0 * e0 + s1.a0 * e1;
    float a1 = s0.a1 * e0 + s1.a1 * e1;
    float a2 = s0.a2 * e0 + s1.a2 * e1;
    float a3 = s0.a3 * e0 + s1.a3 * e1;

    float4 bi4 = *(const float4*)&bias[c0];
    float inv = 1.0f / s;
    float gg0 = a0 * inv + bi4.x;
    float gg1 = a1 * inv + bi4.y;
    float gg2 = a2 * inv + bi4.z;
    float gg3 = a3 * inv + bi4.w;

    float lsum = gg0 + gg1 + gg2 + gg3;
#pragma unroll
    for (int off = 16; off >= 1; off >>= 1) lsum += __shfl_xor_sync(0xffffffffu, lsum, off);
    float mean = lsum * (1.0f / 128.0f);
    float d0 = gg0 - mean, d1 = gg1 - mean, d2 = gg2 - mean, d3 = gg3 - mean;
    float lsq = d0 * d0 + d1 * d1 + d2 * d2 + d3 * d3;
#pragma unroll
    for (int off = 16; off >= 1; off >>= 1) lsq += __shfl_xor_sync(0xffffffffu, lsq, off);
    float var = lsq * (1.0f / 128.0f);
    float rstd = rsqrtf(var + 1e-5f);

    float4 ga4 = *(const float4*)&gamma[c0];
    float4 be4 = *(const float4*)&beta[c0];
    float y0 = d0 * rstd * ga4.x + be4.x;
    float y1 = d1 * rstd * ga4.y + be4.y;
    float y2 = d2 * rstd * ga4.z + be4.z;
    float y3 = d3 * rstd * ga4.w + be4.w;
    y0 = (y0 > 0.f) ? y0 : expm1f(y0);
    y1 = (y1 > 0.f) ? y1 : expm1f(y1);
    y2 = (y2 > 0.f) ? y2 : expm1f(y2);
    y3 = (y3 > 0.f) ? y3 : expm1f(y3);

    float4 hv = *(const float4*)&hin[(long long)node * D + c0];
    float4 o;
    o.x = hv.x + y0;
    o.y = hv.y + y1;
    o.z = hv.z + y2;
    o.w = hv.w + y3;
    *(float4*)&hout[(long long)node * D + c0] = o;
}

// ---------------- launch ------------------------------------------------------
extern "C" void kernel_launch(void* const* d_in, const int* in_sizes, int n_in,
                              void* d_out, int out_size) {
    const float* x = (const float*)d_in[0];
    const void* ei = (const void*)d_in[1];
    const float* Wl = (const float*)d_in[2];
    const float* Wr = (const float*)d_in[3];
    const float* att = (const float*)d_in[4];
    const float* bias = (const float*)d_in[5];
    const float* gamma = (const float*)d_in[6];
    const float* beta = (const float*)d_in[7];
    float* out = (float*)d_out;

    int N = in_sizes[0] / D;
    long long E = (long long)in_sizes[1] / 2;
    int nb = (N + 1023) / 1024;

    // sort edges by destination (counting sort), detect index dtype
    k_detect<<<1, 32>>>((const unsigned int*)ei);
    k_zero<<<(N + 255) / 256, 256>>>(N);
    int eg = (int)((E + 255) / 256);
    k_hist<<<eg, 256>>>(ei, E);
    k_blksum<<<nb, 256>>>(N);
    k_scan2<<<1, 128>>>(nb);
    k_starts<<<nb, 256>>>(N);
    k_scatter<<<eg, 256>>>(ei, E);

    dim3 gg((N + 63) / 64, 2);
    int ewarps = (N + 7) / 8;

    // layer 0
    k_gemm<<<gg, 256>>>(x, 0, Wl, Wr, N);
    k_edge<<<ewarps, 256>>>(x, 0, out, 1, att, bias, gamma, beta, N);
    // layer 1
    k_gemm<<<gg, 256>>>(x, 1, Wl + D * D, Wr + D * D, N);
    k_edge<<<ewarps, 256>>>(x, 1, out, 0, att + NH * 32, bias + D, gamma + D,
                            beta + D, N);
}

// round 3
// speedup vs baseline: 2.4271x; 1.2666x over previous
#include <cuda_runtime.h>
#include <cuda_bf16.h>
#include <math.h>

#define D 128
#define NH 4
#define MAXN 100352
#define MAXE 1700000
#define LDS_W 136  // padded bf16 row stride (272B -> conflict-free ldmatrix)
#define TILE_ELEMS (128 * LDS_W)

// ---------------- scratch (static device globals; no allocations) -------------
__device__ float g_xl[MAXN * D];
__device__ float g_xr[MAXN * D];
__device__ float g_h[MAXN * D];
__device__ int   g_src[MAXE];
__device__ int   g_counts[MAXN];
__device__ int   g_starts[MAXN];
__device__ int   g_cursor[MAXN];
__device__ int   g_bsum[128];
__device__ int   g_boff[128];
__device__ int   g_is64;

// ---------------- edge-index dtype detection ---------------------------------
__global__ void k_detect(const unsigned int* __restrict__ e) {
    unsigned int w = e[2 * threadIdx.x + 1];
    unsigned int b = __ballot_sync(0xffffffffu, w == 0u);
    if (threadIdx.x == 0) g_is64 = (b == 0xffffffffu) ? 1 : 0;
}

__global__ void k_zero(int n) {
    int i = blockIdx.x * blockDim.x + threadIdx.x;
    if (i < n) g_counts[i] = 0;
}

__device__ __forceinline__ int edge_at(const void* e, int is64, long long idx) {
    if (is64) return (int)((const long long*)e)[idx];
    return ((const int*)e)[idx];
}

__global__ void k_hist(const void* __restrict__ e, long long E) {
    long long i = (long long)blockIdx.x * blockDim.x + threadIdx.x;
    if (i >= E) return;
    int is64 = g_is64;
    int d = edge_at(e, is64, E + i);
    atomicAdd(&g_counts[d], 1);
}

// ---- hierarchical scan ------------------------------------------------------
__global__ __launch_bounds__(256) void k_blksum(int n) {
    __shared__ int sh[256];
    int b = blockIdx.x, t = threadIdx.x;
    int base = b * 1024;
    int s = 0;
#pragma unroll
    for (int j = 0; j < 4; j++) {
        int i = base + t + j * 256;
        if (i < n) s += g_counts[i];
    }
    sh[t] = s;
    __syncthreads();
    for (int off = 128; off >= 1; off >>= 1) {
        if (t < off) sh[t] += sh[t + off];
        __syncthreads();
    }
    if (t == 0) g_bsum[b] = sh[0];
}

__global__ __launch_bounds__(128) void k_scan2(int nb) {
    __shared__ int sh[128];
    int t = threadIdx.x;
    sh[t] = (t < nb) ? g_bsum[t] : 0;
    __syncthreads();
    if (t == 0) {
        int run = 0;
        for (int i = 0; i < nb; i++) {
            int c = sh[i];
            g_boff[i] = run;
            run += c;
        }
    }
}

__global__ __launch_bounds__(256) void k_starts(int n) {
    __shared__ int ssum[256];
    int b = blockIdx.x, t = threadIdx.x;
    int base = b * 1024 + t * 4;
    int c0 = 0, c1 = 0, c2 = 0, c3 = 0;
    if (base + 0 < n) c0 = g_counts[base + 0];
    if (base + 1 < n) c1 = g_counts[base + 1];
    if (base + 2 < n) c2 = g_counts[base + 2];
    if (base + 3 < n) c3 = g_counts[base + 3];
    ssum[t] = c0 + c1 + c2 + c3;
    __syncthreads();
    for (int off = 1; off < 256; off <<= 1) {
        int v = (t >= off) ? ssum[t - off] : 0;
        __syncthreads();
        ssum[t] += v;
        __syncthreads();
    }
    int run = g_boff[b] + ((t == 0) ? 0 : ssum[t - 1]);
    if (base + 0 < n) { g_starts[base + 0] = run; g_cursor[base + 0] = run; run += c0; }
    if (base + 1 < n) { g_starts[base + 1] = run; g_cursor[base + 1] = run; run += c1; }
    if (base + 2 < n) { g_starts[base + 2] = run; g_cursor[base + 2] = run; run += c2; }
    if (base + 3 < n) { g_starts[base + 3] = run; g_cursor[base + 3] = run; run += c3; }
}

__global__ void k_scatter(const void* __restrict__ e, long long E) {
    long long i = (long long)blockIdx.x * blockDim.x + threadIdx.x;
    if (i >= E) return;
    int is64 = g_is64;
    int s = edge_at(e, is64, i);
    int d = edge_at(e, is64, E + i);
    int pos = atomicAdd(&g_cursor[d], 1);
    g_src[pos] = s;
}

// ---------------- tensor-core GEMM (bf16 3-split): xl & xr fused -------------
__device__ __forceinline__ void ldsm4(unsigned* r, unsigned addr) {
    asm volatile("ldmatrix.sync.aligned.m8n8.x4.shared.b16 {%0,%1,%2,%3}, [%4];"
                 : "=r"(r[0]), "=r"(r[1]), "=r"(r[2]), "=r"(r[3]) : "r"(addr));
}
__device__ __forceinline__ void ldsm4t(unsigned* r, unsigned addr) {
    asm volatile("ldmatrix.sync.aligned.m8n8.x4.trans.shared.b16 {%0,%1,%2,%3}, [%4];"
                 : "=r"(r[0]), "=r"(r[1]), "=r"(r[2]), "=r"(r[3]) : "r"(addr));
}
__device__ __forceinline__ void mma_bf16(float* c, const unsigned* a, unsigned b0,
                                         unsigned b1) {
    asm volatile(
        "mma.sync.aligned.m16n8k16.row.col.f32.bf16.bf16.f32 "
        "{%0,%1,%2,%3}, {%4,%5,%6,%7}, {%8,%9}, {%0,%1,%2,%3};"
        : "+f"(c[0]), "+f"(c[1]), "+f"(c[2]), "+f"(c[3])
        : "r"(a[0]), "r"(a[1]), "r"(a[2]), "r"(a[3]), "r"(b0), "r"(b1));
}

__device__ __forceinline__ void cvt_store4(__nv_bfloat16* hi, __nv_bfloat16* lo,
                                           int addr, float4 v) {
    __nv_bfloat16 h0 = __float2bfloat16(v.x), h1 = __float2bfloat16(v.y);
    __nv_bfloat16 h2 = __float2bfloat16(v.z), h3 = __float2bfloat16(v.w);
    __nv_bfloat16 l0 = __float2bfloat16(v.x - __bfloat162float(h0));
    __nv_bfloat16 l1 = __float2bfloat16(v.y - __bfloat162float(h1));
    __nv_bfloat16 l2 = __float2bfloat16(v.z - __bfloat162float(h2));
    __nv_bfloat16 l3 = __float2bfloat16(v.w - __bfloat162float(h3));
    *(__nv_bfloat162*)&hi[addr] = __nv_bfloat162(h0, h1);
    *(__nv_bfloat162*)&hi[addr + 2] = __nv_bfloat162(h2, h3);
    *(__nv_bfloat162*)&lo[addr] = __nv_bfloat162(l0, l1);
    *(__nv_bfloat162*)&lo[addr + 2] = __nv_bfloat162(l2, l3);
}

// smem bf16 layout: [AHI][ALO][WL_HI][WL_LO][WR_HI][WR_LO], each 128*136
#define SMEM_BYTES (6 * TILE_ELEMS * 2)

__global__ __launch_bounds__(256, 1) void k_gemm_tc(const float* __restrict__ A_ext,
                                                    int a_internal,
                                                    const float* __restrict__ WL,
                                                    const float* __restrict__ WR,
                                                    int M) {
    extern __shared__ __nv_bfloat16 sm[];
    __nv_bfloat16* sAhi = sm;
    __nv_bfloat16* sAlo = sm + TILE_ELEMS;
    const float* A = a_internal ? g_h : A_ext;
    int row0 = blockIdx.x * 128;
    int tid = threadIdx.x;

    // convert Wl and Wr into smem (hi/lo)
#pragma unroll
    for (int o = 0; o < 2; o++) {
        const float* W = o ? WR : WL;
        __nv_bfloat16* hi = sm + (2 + o * 2) * TILE_ELEMS;
        __nv_bfloat16* lo = hi + TILE_ELEMS;
#pragma unroll
        for (int j = 0; j < 16; j++) {
            int idx = tid + j * 256;  // 4096 float4 = 128 x 32
            int k = idx >> 5, n4 = (idx & 31) * 4;
            float4 v = ((const float4*)W)[idx];
            cvt_store4(hi, lo, k * LDS_W + n4, v);
        }
    }
    // convert A tile (128 rows), zero-padded past M
#pragma unroll
    for (int j = 0; j < 16; j++) {
        int idx = tid + j * 256;
        int r = idx >> 5, c4 = (idx & 31) * 4;
        float4 v = make_float4(0.f, 0.f, 0.f, 0.f);
        if (row0 + r < M) v = ((const float4*)(A + (long long)(row0 + r) * D))[idx & 31];
        cvt_store4(sAhi, sAlo, r * LDS_W + c4, v);
    }
    __syncthreads();

    int lane = tid & 31, w = tid >> 5;
    int wm = w & 3, wn = w >> 2;  // warp tile: rows wm*32, cols wn*64
    int r8 = lane & 7, s01 = (lane >> 3) & 1, sk = lane >> 4;

    float c[2][2][8][4];
#pragma unroll
    for (int o = 0; o < 2; o++)
#pragma unroll
        for (int i = 0; i < 2; i++)
#pragma unroll
            for (int j = 0; j < 8; j++)
#pragma unroll
                for (int q = 0; q < 4; q++) c[o][i][j][q] = 0.f;

    unsigned base = (unsigned)__cvta_generic_to_shared(sm);

    for (int ks = 0; ks < 8; ks++) {
        int k0 = ks * 16;
        unsigned ahi[2][4], alo[2][4];
#pragma unroll
        for (int i = 0; i < 2; i++) {
            int row = wm * 32 + i * 16 + s01 * 8 + r8;
            int col = k0 + sk * 8;
            unsigned off = (unsigned)(row * LDS_W + col) * 2u;
            ldsm4(ahi[i], base + off);
            ldsm4(alo[i], base + TILE_ELEMS * 2 + off);
        }
#pragma unroll
        for (int o = 0; o < 2; o++) {
#pragma unroll
            for (int jj = 0; jj < 4; jj++) {
                int n0 = wn * 64 + jj * 16;
                int rowk = k0 + s01 * 8 + r8;
                int coln = n0 + sk * 8;
                unsigned woff = (unsigned)(rowk * LDS_W + coln) * 2u;
                unsigned bhi[4], blo[4];
                ldsm4t(bhi, base + (2 + o * 2) * TILE_ELEMS * 2 + woff);
                ldsm4t(blo, base + (3 + o * 2) * TILE_ELEMS * 2 + woff);
#pragma unroll
                for (int i = 0; i < 2; i++) {
                    mma_bf16(c[o][i][jj * 2], ahi[i], bhi[0], bhi[1]);
                    mma_bf16(c[o][i][jj * 2], ahi[i], blo[0], blo[1]);
                    mma_bf16(c[o][i][jj * 2], alo[i], bhi[0], bhi[1]);
                    mma_bf16(c[o][i][jj * 2 + 1], ahi[i], bhi[2], bhi[3]);
                    mma_bf16(c[o][i][jj * 2 + 1], ahi[i], blo[2], blo[3]);
                    mma_bf16(c[o][i][jj * 2 + 1], alo[i], bhi[2], bhi[3]);
                }
            }
        }
    }

    // epilogue
#pragma unroll
    for (int o = 0; o < 2; o++) {
        float* Out = o ? g_xr : g_xl;
#pragma unroll
        for (int i = 0; i < 2; i++) {
#pragma unroll
            for (int j = 0; j < 8; j++) {
                int row = row0 + wm * 32 + i * 16 + (lane >> 2);
                int col = wn * 64 + j * 8 + (lane & 3) * 2;
                if (row < M)
                    *(float2*)&Out[(long long)row * D + col] =
                        make_float2(c[o][i][j][0], c[o][i][j][1]);
                if (row + 8 < M)
                    *(float2*)&Out[(long long)(row + 8) * D + col] =
                        make_float2(c[o][i][j][2], c[o][i][j][3]);
            }
        }
    }
}

// ---------------- fused edge attention + aggregate + LN + ELU + residual -----
__device__ __forceinline__ float edge_alpha(float4 xl4, float4 xr4, float4 at4) {
    float t0 = xl4.x + xr4.x; t0 = fmaxf(t0, 0.2f * t0);
    float t1 = xl4.y + xr4.y; t1 = fmaxf(t1, 0.2f * t1);
    float t2 = xl4.z + xr4.z; t2 = fmaxf(t2, 0.2f * t2);
    float t3 = xl4.w + xr4.w; t3 = fmaxf(t3, 0.2f * t3);
    float p = t0 * at4.x + t1 * at4.y + t2 * at4.z + t3 * at4.w;
    p += __shfl_xor_sync(0xffffffffu, p, 1);
    p += __shfl_xor_sync(0xffffffffu, p, 2);
    p += __shfl_xor_sync(0xffffffffu, p, 4);
    return p;
}

struct SoftState { float m, s, a0, a1, a2, a3; };

__device__ __forceinline__ void upd(SoftState& st, float4 cur, float4 xr4,
                                    float4 at4) {
    float alpha = edge_alpha(cur, xr4, at4);
    float nm = fmaxf(st.m, alpha);
    float sc = __expf(st.m - nm);
    float p = __expf(alpha - nm);
    st.s = st.s * sc + p;
    st.a0 = st.a0 * sc + p * cur.x;
    st.a1 = st.a1 * sc + p * cur.y;
    st.a2 = st.a2 * sc + p * cur.z;
    st.a3 = st.a3 * sc + p * cur.w;
    st.m = nm;
}

__global__ __launch_bounds__(256) void k_edge(const float* __restrict__ hin_ext,
                                              int hin_internal,
                                              float* __restrict__ hout_ext,
                                              int hout_internal,
                                              const float* __restrict__ att,
                                              const float* __restrict__ bias,
                                              const float* __restrict__ gamma,
                                              const float* __restrict__ beta,
                                              int n) {
    int node = (blockIdx.x * blockDim.x + threadIdx.x) >> 5;
    int lane = threadIdx.x & 31;
    if (node >= n) return;
    const float* hin = hin_internal ? g_h : hin_ext;
    float* hout = hout_internal ? g_h : hout_ext;
    const int c0 = lane * 4;

    float4 xr4 = *(const float4*)&g_xr[(long long)node * D + c0];
    float4 at4 = *(const float4*)&att[c0];

    float4 xv = *(const float4*)&g_xl[(long long)node * D + c0];
    SoftState s0, s1;
    s0.m = edge_alpha(xv, xr4, at4);
    s0.s = 1.0f;
    s0.a0 = xv.x; s0.a1 = xv.y; s0.a2 = xv.z; s0.a3 = xv.w;
    s1.m = -1e30f; s1.s = 0.f;
    s1.a0 = 0.f; s1.a1 = 0.f; s1.a2 = 0.f; s1.a3 = 0.f;

    int beg = g_starts[node];
    int cnt = g_counts[node];

    float4 pf0 = make_float4(0.f, 0.f, 0.f, 0.f);
    float4 pf1 = make_float4(0.f, 0.f, 0.f, 0.f);
    if (cnt > 0) pf0 = *(const float4*)&g_xl[(long long)g_src[beg] * D + c0];
    if (cnt > 1) pf1 = *(const float4*)&g_xl[(long long)g_src[beg + 1] * D + c0];

    int k = 0;
    for (; k + 1 < cnt; k += 2) {
        float4 c0v = pf0, c1v = pf1;
        if (k + 2 < cnt) pf0 = *(const float4*)&g_xl[(long long)g_src[beg + k + 2] * D + c0];
        if (k + 3 < cnt) pf1 = *(const float4*)&g_xl[(long long)g_src[beg + k + 3] * D + c0];
        upd(s0, c0v, xr4, at4);
        upd(s1, c1v, xr4, at4);
    }
    if (k < cnt) upd(s0, pf0, xr4, at4);

    float M = fmaxf(s0.m, s1.m);
    float e0 = __expf(s0.m - M), e1 = __expf(s1.m - M);
    float s = s0.s * e0 + s1.s * e1;
    float a0 = s0.a0 * e0 + s1.a0 * e1;
    float a1 = s0.a1 * e0 + s1.a1 * e1;
    float a2 = s0.a2 * e0 + s1.a2 * e1;
    float a3 = s0.a3 * e0 + s1.a3 * e1;

    float4 bi4 = *(const float4*)&bias[c0];
    float inv = 1.0f / s;
    float gg0 = a0 * inv + bi4.x;
    float gg1 = a1 * inv + bi4.y;
    float gg2 = a2 * inv + bi4.z;
    float gg3 = a3 * inv + bi4.w;

    float lsum = gg0 + gg1 + gg2 + gg3;
#pragma unroll
    for (int off = 16; off >= 1; off >>= 1) lsum += __shfl_xor_sync(0xffffffffu, lsum, off);
    float mean = lsum * (1.0f / 128.0f);
    float d0 = gg0 - mean, d1 = gg1 - mean, d2 = gg2 - mean, d3 = gg3 - mean;
    float lsq = d0 * d0 + d1 * d1 + d2 * d2 + d3 * d3;
#pragma unroll
    for (int off = 16; off >= 1; off >>= 1) lsq += __shfl_xor_sync(0xffffffffu, lsq, off);
    float var = lsq * (1.0f / 128.0f);
    float rstd = rsqrtf(var + 1e-5f);

    float4 ga4 = *(const float4*)&gamma[c0];
    float4 be4 = *(const float4*)&beta[c0];
    float y0 = d0 * rstd * ga4.x + be4.x;
    float y1 = d1 * rstd * ga4.y + be4.y;
    float y2 = d2 * rstd * ga4.z + be4.z;
    float y3 = d3 * rstd * ga4.w + be4.w;
    y0 = (y0 > 0.f) ? y0 : expm1f(y0);
    y1 = (y1 > 0.f) ? y1 : expm1f(y1);
    y2 = (y2 > 0.f) ? y2 : expm1f(y2);
    y3 = (y3 > 0.f) ? y3 : expm1f(y3);

    float4 hv = *(const float4*)&hin[(long long)node * D + c0];
    float4 o;
    o.x = hv.x + y0;
    o.y = hv.y + y1;
    o.z = hv.z + y2;
    o.w = hv.w + y3;
    *(float4*)&hout[(long long)node * D + c0] = o;
}

// ---------------- launch ------------------------------------------------------
extern "C" void kernel_launch(void* const* d_in, const int* in_sizes, int n_in,
                              void* d_out, int out_size) {
    const float* x = (const float*)d_in[0];
    const void* ei = (const void*)d_in[1];
    const float* Wl = (const float*)d_in[2];
    const float* Wr = (const float*)d_in[3];
    const float* att = (const float*)d_in[4];
    const float* bias = (const float*)d_in[5];
    const float* gamma = (const float*)d_in[6];
    const float* beta = (const float*)d_in[7];
    float* out = (float*)d_out;

    int N = in_sizes[0] / D;
    long long E = (long long)in_sizes[1] / 2;
    int nb = (N + 1023) / 1024;

    static int smem_set = 0;
    if (!smem_set) {
        cudaFuncSetAttribute(k_gemm_tc, cudaFuncAttributeMaxDynamicSharedMemorySize,
                             SMEM_BYTES);
        smem_set = 1;
    }

    k_detect<<<1, 32>>>((const unsigned int*)ei);
    k_zero<<<(N + 255) / 256, 256>>>(N);
    int eg = (int)((E + 255) / 256);
    k_hist<<<eg, 256>>>(ei, E);
    k_blksum<<<nb, 256>>>(N);
    k_scan2<<<1, 128>>>(nb);
    k_starts<<<nb, 256>>>(N);
    k_scatter<<<eg, 256>>>(ei, E);

    int gb = (N + 127) / 128;
    int ewarps = (N + 7) / 8;

    // layer 0
    k_gemm_tc<<<gb, 256, SMEM_BYTES>>>(x, 0, Wl, Wr, N);
    k_edge<<<ewarps, 256>>>(x, 0, out, 1, att, bias, gamma, beta, N);
    // layer 1
    k_gemm_tc<<<gb, 256, SMEM_BYTES>>>(x, 1, Wl + D * D, Wr + D * D, N);
    k_edge<<<ewarps, 256>>>(x, 1, out, 0, att + NH * 32, bias + D, gamma + D,
                            beta + D, N);
}